// round 13
// baseline (speedup 1.0000x reference)
#include <cuda_runtime.h>
#include <cuda_fp16.h>
#include <math.h>
#include <stdint.h>

// ---------------------------------------------------------------------------
// Scratch (static device arrays; no allocation allowed).
// ---------------------------------------------------------------------------
__device__ __half g_x16[32u * 512u * 512u];    // x  as f16   [B][T][D]
__device__ __half g_h16[32u * 512u * 1024u];   // h  as f16   [B][T][MID]
__device__ __half g_w1h[64u * 512u * 1024u];   // w1 f16      [S][K=D][N=MID]
__device__ __half g_w2h[64u * 1024u * 512u];   // w2 f16      [S][K=MID][N=O]

// ---------------------------------------------------------------------------
// helpers
// ---------------------------------------------------------------------------
__device__ __forceinline__ uint32_t smem_u32(const void* p) {
    uint32_t a;
    asm("{ .reg .u64 t; cvta.to.shared.u64 t, %1; cvt.u32.u64 %0, t; }"
        : "=r"(a) : "l"(p));
    return a;
}

__device__ __forceinline__ void cp_async16(uint32_t saddr, const void* gptr) {
    asm volatile("cp.async.cg.shared.global [%0], [%1], 16;"
                 :: "r"(saddr), "l"(gptr) : "memory");
}
__device__ __forceinline__ void cp_commit() {
    asm volatile("cp.async.commit_group;" ::: "memory");
}
template <int N>
__device__ __forceinline__ void cp_wait() {
    asm volatile("cp.async.wait_group %0;" :: "n"(N) : "memory");
}

__device__ __forceinline__ void ldsm_x4(uint32_t r[4], uint32_t addr) {
    asm volatile("ldmatrix.sync.aligned.m8n8.x4.shared.b16 {%0,%1,%2,%3}, [%4];"
                 : "=r"(r[0]), "=r"(r[1]), "=r"(r[2]), "=r"(r[3])
                 : "r"(addr));
}
__device__ __forceinline__ void ldsm_x4_t(uint32_t r[4], uint32_t addr) {
    asm volatile("ldmatrix.sync.aligned.m8n8.x4.trans.shared.b16 {%0,%1,%2,%3}, [%4];"
                 : "=r"(r[0]), "=r"(r[1]), "=r"(r[2]), "=r"(r[3])
                 : "r"(addr));
}

__device__ __forceinline__ void mma_f16(float c[4], const uint32_t a[4],
                                        uint32_t b0, uint32_t b1) {
    asm volatile(
        "mma.sync.aligned.m16n8k16.row.col.f32.f16.f16.f32 "
        "{%0,%1,%2,%3}, {%4,%5,%6,%7}, {%8,%9}, {%0,%1,%2,%3};"
        : "+f"(c[0]), "+f"(c[1]), "+f"(c[2]), "+f"(c[3])
        : "r"(a[0]), "r"(a[1]), "r"(a[2]), "r"(a[3]), "r"(b0), "r"(b1));
}

// sid dtype sniff (int32 vs int64), proven in rounds 4-11.
__device__ __forceinline__ int load_sid(const int* __restrict__ raw, int b) {
    bool is64 = true;
    #pragma unroll
    for (int i = 0; i < 16; i++)
        if (raw[2 * i + 1] != 0) { is64 = false; break; }
    int s = is64 ? raw[2 * b] : raw[b];
    if (s < 0) s = 0;
    if (s > 63) s = 63;
    return s;
}

__device__ __forceinline__ bool subject_used(const int* __restrict__ raw, int s) {
    bool is64 = true;
    #pragma unroll
    for (int i = 0; i < 16; i++)
        if (raw[2 * i + 1] != 0) { is64 = false; break; }
    #pragma unroll
    for (int b = 0; b < 32; b++) {
        int v = is64 ? raw[2 * b] : raw[b];
        if (v == s) return true;
    }
    return false;
}

// ---------------------------------------------------------------------------
// Conversion kernels (pure streaming)
// ---------------------------------------------------------------------------
__global__ void convert_x_kernel(const float4* __restrict__ in,
                                 uint2* __restrict__ out, int n4) {
    for (int i = blockIdx.x * blockDim.x + threadIdx.x; i < n4;
         i += gridDim.x * blockDim.x) {
        float4 v = in[i];
        __half2 lo = __floats2half2_rn(v.x, v.y);
        __half2 hi = __floats2half2_rn(v.z, v.w);
        uint2 u;
        u.x = *reinterpret_cast<uint32_t*>(&lo);
        u.y = *reinterpret_cast<uint32_t*>(&hi);
        out[i] = u;
    }
}

// w [S][K][N] f32 -> f16 same layout, used subjects only.
__global__ void convert_w_kernel(const float4* __restrict__ in,
                                 uint2* __restrict__ out,
                                 const int* __restrict__ sid_raw,
                                 int elems4_per_subject) {
    const int s = blockIdx.z;
    if (!subject_used(sid_raw, s)) return;
    const float4* ip = in + (size_t)s * elems4_per_subject;
    uint2* op = out + (size_t)s * elems4_per_subject;
    for (int i = blockIdx.x * blockDim.x + threadIdx.x; i < elems4_per_subject;
         i += gridDim.x * blockDim.x) {
        float4 v = ip[i];
        __half2 lo = __floats2half2_rn(v.x, v.y);
        __half2 hi = __floats2half2_rn(v.z, v.w);
        uint2 u;
        u.x = *reinterpret_cast<uint32_t*>(&lo);
        u.y = *reinterpret_cast<uint32_t*>(&hi);
        op[i] = u;
    }
}

// ---------------------------------------------------------------------------
// fp16 mma.sync GEMM. BK=16, 5-stage cp.async pipeline, B-fragment register
// ping-pong. Iteration order (the r12 NaN fix): cp_wait -> __syncthreads ->
// LDSM reads (stage c A, stage c+1 B prefetch) -> MMA -> issue/commit.
//   - Reads are barrier-published: wait guarantees stages <= c+1 complete in
//     this thread; the barrier right after publishes all threads' copies.
//   - Overwrite of slot (c-1)%5 at iter end is safe: its last readers ran in
//     iters c-1 / c-2, strictly before this iter's top barrier.
//   C[b] = act( A[b] @ W[sid[b]] ) (+ bias[sid[b]])
//   A: [B, M, K] f16 (K contig) -> ldmatrix;  W: [S, K, N] f16 (N contig)
//   -> ldmatrix.trans.  CTA 128x128, 256 thr (8 warps 4(m)x2(n), warp 32x64).
// ---------------------------------------------------------------------------
#define NSTAGE 5
static constexpr int A_ROW_B = 48;
static constexpr int B_ROW_B = 272;
static constexpr int A_STG = 128 * A_ROW_B;       // 6144 B
static constexpr int B_STG = 16 * B_ROW_B;        // 4352 B
static constexpr int STG_B = A_STG + B_STG;       // 10496 B
static constexpr int SMEM_DYN = NSTAGE * STG_B;   // 52480 B

template <bool DO_GELU, bool DO_BIAS, bool STORE_HALF>
__global__ __launch_bounds__(256, 2)
void subject_hgemm(const __half* __restrict__ A_base,
                   const __half* __restrict__ W_base,
                   const int* __restrict__ sid_raw,
                   const float* __restrict__ bias_base,
                   void* __restrict__ C_base,
                   int M, int N, int K)
{
    const int b = blockIdx.z;
    const int s = load_sid(sid_raw, b);
    const __half* A = A_base + (size_t)b * M * K;
    const __half* W = W_base + (size_t)s * K * N;
    const int m0 = blockIdx.y * 128;
    const int n0 = blockIdx.x * 128;

    extern __shared__ char dsm[];
    const uint32_t smem0 = smem_u32(dsm);

    const int tid = threadIdx.x;
    const int wid = tid >> 5;
    const int lane = tid & 31;
    const int wm = wid >> 1;   // 0..3 -> 32-row slab
    const int wn = wid & 1;    // 0..1 -> 64-col slab
    const int g = lane >> 2;   // 0..7
    const int t4 = lane & 3;   // 0..3

    // cp.async A: thread -> m-row tid>>1, 16B half tid&1.
    const int aR = tid >> 1, aH = tid & 1;
    const __half* Ag = A + (size_t)(m0 + aR) * K + aH * 8;
    const uint32_t cpOffA = (uint32_t)(aR * A_ROW_B + aH * 16);
    // cp.async B: thread -> k-row tid>>4, 16B segment tid&15 (coalesced in n).
    const int bR = tid >> 4, bS = tid & 15;
    const __half* Bg = W + (size_t)bR * N + n0 + bS * 8;
    const uint32_t cpOffB = (uint32_t)(A_STG + bR * B_ROW_B + bS * 16);

    // ldmatrix lane addresses.
    const uint32_t aAddr0 = smem0
        + (uint32_t)((wm * 32 + (lane & 15)) * A_ROW_B + (lane >> 4) * 16);
    const int bRow = ((lane >> 3) & 1) * 8 + (lane & 7);  // k row within 16
    const int bNh = (lane >> 4) * 8;                       // n sub-offset
    const uint32_t bAddr0 = smem0
        + (uint32_t)(A_STG + bRow * B_ROW_B + (wn * 64 + bNh) * 2);

    const int NC = K / 16;

    auto issue_stage = [&](int c) {
        const uint32_t base = smem0 + (uint32_t)((c % NSTAGE) * STG_B);
        const int k0 = c * 16;
        cp_async16(base + cpOffA, Ag + k0);
        cp_async16(base + cpOffB, Bg + (size_t)k0 * N);
    };

    float acc[2][8][4];
    #pragma unroll
    for (int i = 0; i < 2; i++)
        #pragma unroll
        for (int j = 0; j < 8; j++)
            #pragma unroll
            for (int q = 0; q < 4; q++)
                acc[i][j][q] = 0.0f;

    // Prologue: fill 4 stages; preload chunk-0 B fragments.
    #pragma unroll
    for (int c = 0; c < NSTAGE - 1; c++) {
        issue_stage(c);
        cp_commit();
    }

    uint32_t bf[2][4][4];  // ping-pong B fragments

    cp_wait<3>();          // stage 0 complete (own copies)
    __syncthreads();       // publish all threads' stage-0 copies
    #pragma unroll
    for (int j = 0; j < 4; j++)
        ldsm_x4_t(bf[0][j], bAddr0 + (uint32_t)(j * 32));

    #pragma unroll 1
    for (int c = 0; c < NC; c++) {
        // Groups committed so far: 4 + c. After wait<2>, stages <= c+1 are
        // complete in this thread's view...
        cp_wait<2>();
        // ...and the barrier publishes every thread's copies for stages
        // <= c+1 before anyone reads them below.
        __syncthreads();

        const uint32_t soffC = (uint32_t)((c % NSTAGE) * STG_B);

        // Current A fragments (stage c).
        uint32_t af[2][4];
        ldsm_x4(af[0], aAddr0 + soffC);
        ldsm_x4(af[1], aAddr0 + soffC + 16 * A_ROW_B);

        // Prefetch next chunk's B fragments (stage c+1) into the other buffer.
        const int cur = c & 1, nxt = cur ^ 1;
        if (c + 1 < NC) {
            const uint32_t soffN = (uint32_t)(((c + 1) % NSTAGE) * STG_B);
            #pragma unroll
            for (int j = 0; j < 4; j++)
                ldsm_x4_t(bf[nxt][j], bAddr0 + soffN + (uint32_t)(j * 32));
        }

        // MMAs for chunk c: B fragments already in registers (prefetched
        // last iteration), A fragments have ~LDS-latency exposure only.
        #pragma unroll
        for (int fm = 0; fm < 2; fm++)
            #pragma unroll
            for (int j = 0; j < 4; j++) {
                mma_f16(acc[fm][2 * j + 0], af[fm], bf[cur][j][0], bf[cur][j][1]);
                mma_f16(acc[fm][2 * j + 1], af[fm], bf[cur][j][2], bf[cur][j][3]);
            }

        // Refill slot (c-1)%5 with stage c+4. Safe: that slot's last readers
        // (A in iter c-1, B-prefetch in iter c-2) ran before this iteration's
        // top barrier, which this thread has already passed.
        if (c + NSTAGE - 1 < NC) issue_stage(c + NSTAGE - 1);
        cp_commit();
    }

    // ---- epilogue ----
    const float* brow = DO_BIAS ? (bias_base + (size_t)s * N + n0) : nullptr;

    #pragma unroll
    for (int fm = 0; fm < 2; fm++) {
        const int r0 = m0 + wm * 32 + fm * 16 + g;
        #pragma unroll
        for (int fn = 0; fn < 8; fn++) {
            const int col = wn * 64 + fn * 8 + t4 * 2;
            #pragma unroll
            for (int h2 = 0; h2 < 2; h2++) {
                const int row = r0 + 8 * h2;
                float v0 = acc[fm][fn][2 * h2 + 0];
                float v1 = acc[fm][fn][2 * h2 + 1];
                if (DO_BIAS) {
                    v0 += brow[col];
                    v1 += brow[col + 1];
                }
                if (DO_GELU) {
                    v0 = 0.5f * v0 * (1.0f + erff(v0 * 0.70710678118654752f));
                    v1 = 0.5f * v1 * (1.0f + erff(v1 * 0.70710678118654752f));
                }
                if (STORE_HALF) {
                    __half2 hv = __floats2half2_rn(v0, v1);
                    *reinterpret_cast<__half2*>(
                        (__half*)C_base + (size_t)b * M * N +
                        (size_t)row * N + n0 + col) = hv;
                } else {
                    *reinterpret_cast<float2*>(
                        (float*)C_base + (size_t)b * M * N +
                        (size_t)row * N + n0 + col) = make_float2(v0, v1);
                }
            }
        }
    }
}

// ---------------------------------------------------------------------------
extern "C" void kernel_launch(void* const* d_in, const int* in_sizes, int n_in,
                              void* d_out, int out_size) {
    const float* x = (const float*)d_in[0];     // [32, 512, 512]
    const int* sid_raw = (const int*)d_in[1];   // [32] int32 or int64 (sniffed)
    const float* w1 = (const float*)d_in[2];    // [64, 512, 1024]
    const float* w2 = (const float*)d_in[3];    // [64, 1024, 512]
    const float* bias = (const float*)d_in[4];  // [64, 512]
    float* out = (float*)d_out;                 // [32, 512, 512]

    const int B = 32, T = 512, D = 512, MID = 1024, O = 512;
    (void)in_sizes; (void)n_in; (void)out_size;

    __half *x16, *h16, *w1h, *w2h;
    cudaGetSymbolAddress((void**)&x16, g_x16);
    cudaGetSymbolAddress((void**)&h16, g_h16);
    cudaGetSymbolAddress((void**)&w1h, g_w1h);
    cudaGetSymbolAddress((void**)&w2h, g_w2h);

    (void)cudaFuncSetAttribute(
        (const void*)subject_hgemm<true, false, true>,
        cudaFuncAttributeMaxDynamicSharedMemorySize, SMEM_DYN);
    (void)cudaFuncSetAttribute(
        (const void*)subject_hgemm<false, true, false>,
        cudaFuncAttributeMaxDynamicSharedMemorySize, SMEM_DYN);

    // 1) x -> f16
    {
        const int n4 = (B * T * D) / 4;
        convert_x_kernel<<<2048, 256>>>((const float4*)x, (uint2*)x16, n4);
    }
    // 2) w1, w2 -> f16 same layout, used subjects only
    {
        const int e4 = (D * MID) / 4;
        convert_w_kernel<<<dim3(128, 1, 64), 256>>>(
            (const float4*)w1, (uint2*)w1h, sid_raw, e4);
        convert_w_kernel<<<dim3(128, 1, 64), 256>>>(
            (const float4*)w2, (uint2*)w2h, sid_raw, e4);
    }
    // 3) GEMM1 + GELU -> h16:  (M=512, N=1024, K=512)
    {
        dim3 grid(MID / 128, T / 128, B);
        subject_hgemm<true, false, true><<<grid, 256, SMEM_DYN>>>(
            x16, w1h, sid_raw, nullptr, (void*)h16, T, MID, D);
    }
    // 4) GEMM2 + bias -> out f32:  (M=512, N=512, K=1024)
    {
        dim3 grid(O / 128, T / 128, B);
        subject_hgemm<false, true, false><<<grid, 256, SMEM_DYN>>>(
            h16, w2h, sid_raw, bias, (void*)out, T, O, MID);
    }
}

// round 14
// speedup vs baseline: 1.5281x; 1.5281x over previous
#include <cuda_runtime.h>
#include <cuda_fp16.h>
#include <math.h>
#include <stdint.h>

// ---------------------------------------------------------------------------
// Scratch (static device arrays; no allocation allowed).
// ---------------------------------------------------------------------------
__device__ __half g_x16[32u * 512u * 512u];    // x  as f16   [B][T][D]
__device__ __half g_h16[32u * 512u * 1024u];   // h  as f16   [B][T][MID]
__device__ __half g_w1h[64u * 512u * 1024u];   // w1 f16      [S][K=D][N=MID]
__device__ __half g_w2h[64u * 1024u * 512u];   // w2 f16      [S][K=MID][N=O]

// ---------------------------------------------------------------------------
// helpers
// ---------------------------------------------------------------------------
__device__ __forceinline__ uint32_t smem_u32(const void* p) {
    uint32_t a;
    asm("{ .reg .u64 t; cvta.to.shared.u64 t, %1; cvt.u32.u64 %0, t; }"
        : "=r"(a) : "l"(p));
    return a;
}

__device__ __forceinline__ void cp_async16(uint32_t saddr, const void* gptr) {
    asm volatile("cp.async.cg.shared.global [%0], [%1], 16;"
                 :: "r"(saddr), "l"(gptr) : "memory");
}
__device__ __forceinline__ void cp_commit() {
    asm volatile("cp.async.commit_group;" ::: "memory");
}
template <int N>
__device__ __forceinline__ void cp_wait() {
    asm volatile("cp.async.wait_group %0;" :: "n"(N) : "memory");
}

__device__ __forceinline__ void ldsm_x4(uint32_t r[4], uint32_t addr) {
    asm volatile("ldmatrix.sync.aligned.m8n8.x4.shared.b16 {%0,%1,%2,%3}, [%4];"
                 : "=r"(r[0]), "=r"(r[1]), "=r"(r[2]), "=r"(r[3])
                 : "r"(addr));
}
__device__ __forceinline__ void ldsm_x4_t(uint32_t r[4], uint32_t addr) {
    asm volatile("ldmatrix.sync.aligned.m8n8.x4.trans.shared.b16 {%0,%1,%2,%3}, [%4];"
                 : "=r"(r[0]), "=r"(r[1]), "=r"(r[2]), "=r"(r[3])
                 : "r"(addr));
}

__device__ __forceinline__ void mma_f16(float c[4], const uint32_t a[4],
                                        uint32_t b0, uint32_t b1) {
    asm volatile(
        "mma.sync.aligned.m16n8k16.row.col.f32.f16.f16.f32 "
        "{%0,%1,%2,%3}, {%4,%5,%6,%7}, {%8,%9}, {%0,%1,%2,%3};"
        : "+f"(c[0]), "+f"(c[1]), "+f"(c[2]), "+f"(c[3])
        : "r"(a[0]), "r"(a[1]), "r"(a[2]), "r"(a[3]), "r"(b0), "r"(b1));
}

// sid dtype sniff (int32 vs int64), proven in rounds 4-13.
__device__ __forceinline__ int load_sid(const int* __restrict__ raw, int b) {
    bool is64 = true;
    #pragma unroll
    for (int i = 0; i < 16; i++)
        if (raw[2 * i + 1] != 0) { is64 = false; break; }
    int s = is64 ? raw[2 * b] : raw[b];
    if (s < 0) s = 0;
    if (s > 63) s = 63;
    return s;
}

__device__ __forceinline__ bool subject_used(const int* __restrict__ raw, int s) {
    bool is64 = true;
    #pragma unroll
    for (int i = 0; i < 16; i++)
        if (raw[2 * i + 1] != 0) { is64 = false; break; }
    #pragma unroll
    for (int b = 0; b < 32; b++) {
        int v = is64 ? raw[2 * b] : raw[b];
        if (v == s) return true;
    }
    return false;
}

// ---------------------------------------------------------------------------
// Conversion kernels (pure streaming)
// ---------------------------------------------------------------------------
__global__ void convert_x_kernel(const float4* __restrict__ in,
                                 uint2* __restrict__ out, int n4) {
    for (int i = blockIdx.x * blockDim.x + threadIdx.x; i < n4;
         i += gridDim.x * blockDim.x) {
        float4 v = in[i];
        __half2 lo = __floats2half2_rn(v.x, v.y);
        __half2 hi = __floats2half2_rn(v.z, v.w);
        uint2 u;
        u.x = *reinterpret_cast<uint32_t*>(&lo);
        u.y = *reinterpret_cast<uint32_t*>(&hi);
        out[i] = u;
    }
}

// w [S][K][N] f32 -> f16 same layout, used subjects only.
__global__ void convert_w_kernel(const float4* __restrict__ in,
                                 uint2* __restrict__ out,
                                 const int* __restrict__ sid_raw,
                                 int elems4_per_subject) {
    const int s = blockIdx.z;
    if (!subject_used(sid_raw, s)) return;
    const float4* ip = in + (size_t)s * elems4_per_subject;
    uint2* op = out + (size_t)s * elems4_per_subject;
    for (int i = blockIdx.x * blockDim.x + threadIdx.x; i < elems4_per_subject;
         i += gridDim.x * blockDim.x) {
        float4 v = ip[i];
        __half2 lo = __floats2half2_rn(v.x, v.y);
        __half2 hi = __floats2half2_rn(v.z, v.w);
        uint2 u;
        u.x = *reinterpret_cast<uint32_t*>(&lo);
        u.y = *reinterpret_cast<uint32_t*>(&hi);
        op[i] = u;
    }
}

// ---------------------------------------------------------------------------
// fp16 mma.sync GEMM, high-occupancy variant: CTA 128x64, 256 threads
// (8 warps 4(m)x2(n), warp 32x32), <=84 regs -> 3 CTAs/SM = 24 warps/SM.
// BK=16, 5-stage cp.async pipeline, r11-proven sync order:
//   cp_wait -> __syncthreads -> issue next stage -> LDSM -> MMA.
//   A: [B, M, K] f16 (K contig) -> ldmatrix;  W: [S, K, N] f16 (N contig)
//   -> ldmatrix.trans.
//   A rows: 32B data + 16B pad = 48B stride; B rows: 128B data + 16B pad =
//   144B stride (36 words; 36 mod 32 = 4 -> 8-row LDSM phases cover all banks).
// ---------------------------------------------------------------------------
#define NSTAGE 5
static constexpr int A_ROW_B = 48;
static constexpr int B_ROW_B = 144;
static constexpr int A_STG = 128 * A_ROW_B;       // 6144 B
static constexpr int B_STG = 16 * B_ROW_B;        // 2304 B
static constexpr int STG_B = A_STG + B_STG;       // 8448 B
static constexpr int SMEM_DYN = NSTAGE * STG_B;   // 42240 B

template <bool DO_GELU, bool DO_BIAS, bool STORE_HALF>
__global__ __launch_bounds__(256, 3)
void subject_hgemm(const __half* __restrict__ A_base,
                   const __half* __restrict__ W_base,
                   const int* __restrict__ sid_raw,
                   const float* __restrict__ bias_base,
                   void* __restrict__ C_base,
                   int M, int N, int K)
{
    const int b = blockIdx.z;
    const int s = load_sid(sid_raw, b);
    const __half* A = A_base + (size_t)b * M * K;
    const __half* W = W_base + (size_t)s * K * N;
    const int m0 = blockIdx.y * 128;
    const int n0 = blockIdx.x * 64;

    extern __shared__ char dsm[];
    const uint32_t smem0 = smem_u32(dsm);

    const int tid = threadIdx.x;
    const int wid = tid >> 5;
    const int lane = tid & 31;
    const int wm = wid >> 1;   // 0..3 -> 32-row slab
    const int wn = wid & 1;    // 0..1 -> 32-col slab
    const int g = lane >> 2;   // 0..7
    const int t4 = lane & 3;   // 0..3

    // cp.async A: 256 threads x 16B: row tid>>1, half tid&1 (128 rows x 32B).
    const int aR = tid >> 1, aH = tid & 1;
    const __half* Ag = A + (size_t)(m0 + aR) * K + aH * 8;
    const uint32_t cpOffA = (uint32_t)(aR * A_ROW_B + aH * 16);
    // cp.async B: threads 0..127 x 16B: k-row tid>>3, seg tid&7 (16 x 128B).
    const int bR = tid >> 3, bS = tid & 7;
    const __half* Bg = W + (size_t)bR * N + n0 + bS * 8;
    const uint32_t cpOffB = (uint32_t)(A_STG + bR * B_ROW_B + bS * 16);
    const bool doB = (tid < 128);

    // ldmatrix lane addresses.
    const uint32_t aAddr0 = smem0
        + (uint32_t)((wm * 32 + (lane & 15)) * A_ROW_B + (lane >> 4) * 16);
    // B trans x4: lanes 0-7 k0-7/n+0, 8-15 k8-15/n+0, 16-23 k0-7/n+8,
    // 24-31 k8-15/n+8 -> one load covers 16 n-cols x 16 k.
    const int bRow = ((lane >> 3) & 1) * 8 + (lane & 7);
    const int bNh = (lane >> 4) * 8;
    const uint32_t bAddr0 = smem0
        + (uint32_t)(A_STG + bRow * B_ROW_B + (wn * 32 + bNh) * 2);

    const int NC = K / 16;

    auto issue_stage = [&](int c) {
        const uint32_t base = smem0 + (uint32_t)((c % NSTAGE) * STG_B);
        const int k0 = c * 16;
        cp_async16(base + cpOffA, Ag + k0);
        if (doB) cp_async16(base + cpOffB, Bg + (size_t)k0 * N);
    };

    float acc[2][4][4];
    #pragma unroll
    for (int i = 0; i < 2; i++)
        #pragma unroll
        for (int j = 0; j < 4; j++)
            #pragma unroll
            for (int q = 0; q < 4; q++)
                acc[i][j][q] = 0.0f;

    #pragma unroll
    for (int c = 0; c < NSTAGE - 1; c++) {
        issue_stage(c);
        cp_commit();
    }

    #pragma unroll 1
    for (int c = 0; c < NC; c++) {
        cp_wait<NSTAGE - 2>();   // stage c complete (own copies)
        __syncthreads();         // publish all threads' copies

        if (c + NSTAGE - 1 < NC) issue_stage(c + NSTAGE - 1);
        cp_commit();

        const uint32_t soff = (uint32_t)((c % NSTAGE) * STG_B);

        uint32_t af[2][4];
        ldsm_x4(af[0], aAddr0 + soff);
        ldsm_x4(af[1], aAddr0 + soff + 16 * A_ROW_B);

        // bf[j]: n-groups 2j (regs 0,1 = k0-7,k8-15) and 2j+1 (regs 2,3).
        uint32_t bf[2][4];
        ldsm_x4_t(bf[0], bAddr0 + soff);
        ldsm_x4_t(bf[1], bAddr0 + soff + 32);  // +16 n-cols

        #pragma unroll
        for (int fm = 0; fm < 2; fm++)
            #pragma unroll
            for (int j = 0; j < 2; j++) {
                mma_f16(acc[fm][2 * j + 0], af[fm], bf[j][0], bf[j][1]);
                mma_f16(acc[fm][2 * j + 1], af[fm], bf[j][2], bf[j][3]);
            }
    }

    // ---- epilogue ----
    const float* brow = DO_BIAS ? (bias_base + (size_t)s * N + n0) : nullptr;

    #pragma unroll
    for (int fm = 0; fm < 2; fm++) {
        const int r0 = m0 + wm * 32 + fm * 16 + g;
        #pragma unroll
        for (int fn = 0; fn < 4; fn++) {
            const int col = wn * 32 + fn * 8 + t4 * 2;
            #pragma unroll
            for (int h2 = 0; h2 < 2; h2++) {
                const int row = r0 + 8 * h2;
                float v0 = acc[fm][fn][2 * h2 + 0];
                float v1 = acc[fm][fn][2 * h2 + 1];
                if (DO_BIAS) {
                    v0 += brow[col];
                    v1 += brow[col + 1];
                }
                if (DO_GELU) {
                    v0 = 0.5f * v0 * (1.0f + erff(v0 * 0.70710678118654752f));
                    v1 = 0.5f * v1 * (1.0f + erff(v1 * 0.70710678118654752f));
                }
                if (STORE_HALF) {
                    __half2 hv = __floats2half2_rn(v0, v1);
                    *reinterpret_cast<__half2*>(
                        (__half*)C_base + (size_t)b * M * N +
                        (size_t)row * N + n0 + col) = hv;
                } else {
                    *reinterpret_cast<float2*>(
                        (float*)C_base + (size_t)b * M * N +
                        (size_t)row * N + n0 + col) = make_float2(v0, v1);
                }
            }
        }
    }
}

// ---------------------------------------------------------------------------
extern "C" void kernel_launch(void* const* d_in, const int* in_sizes, int n_in,
                              void* d_out, int out_size) {
    const float* x = (const float*)d_in[0];     // [32, 512, 512]
    const int* sid_raw = (const int*)d_in[1];   // [32] int32 or int64 (sniffed)
    const float* w1 = (const float*)d_in[2];    // [64, 512, 1024]
    const float* w2 = (const float*)d_in[3];    // [64, 1024, 512]
    const float* bias = (const float*)d_in[4];  // [64, 512]
    float* out = (float*)d_out;                 // [32, 512, 512]

    const int B = 32, T = 512, D = 512, MID = 1024, O = 512;
    (void)in_sizes; (void)n_in; (void)out_size;

    __half *x16, *h16, *w1h, *w2h;
    cudaGetSymbolAddress((void**)&x16, g_x16);
    cudaGetSymbolAddress((void**)&h16, g_h16);
    cudaGetSymbolAddress((void**)&w1h, g_w1h);
    cudaGetSymbolAddress((void**)&w2h, g_w2h);

    (void)cudaFuncSetAttribute(
        (const void*)subject_hgemm<true, false, true>,
        cudaFuncAttributeMaxDynamicSharedMemorySize, SMEM_DYN);
    (void)cudaFuncSetAttribute(
        (const void*)subject_hgemm<false, true, false>,
        cudaFuncAttributeMaxDynamicSharedMemorySize, SMEM_DYN);

    // 1) x -> f16
    {
        const int n4 = (B * T * D) / 4;
        convert_x_kernel<<<2048, 256>>>((const float4*)x, (uint2*)x16, n4);
    }
    // 2) w1, w2 -> f16 same layout, used subjects only
    {
        const int e4 = (D * MID) / 4;
        convert_w_kernel<<<dim3(128, 1, 64), 256>>>(
            (const float4*)w1, (uint2*)w1h, sid_raw, e4);
        convert_w_kernel<<<dim3(128, 1, 64), 256>>>(
            (const float4*)w2, (uint2*)w2h, sid_raw, e4);
    }
    // 3) GEMM1 + GELU -> h16:  (M=512, N=1024, K=512)
    {
        dim3 grid(MID / 64, T / 128, B);
        subject_hgemm<true, false, true><<<grid, 256, SMEM_DYN>>>(
            x16, w1h, sid_raw, nullptr, (void*)h16, T, MID, D);
    }
    // 4) GEMM2 + bias -> out f32:  (M=512, N=512, K=1024)
    {
        dim3 grid(O / 64, T / 128, B);
        subject_hgemm<false, true, false><<<grid, 256, SMEM_DYN>>>(
            h16, w2h, sid_raw, bias, (void*)out, T, O, MID);
    }
}

// round 16
// speedup vs baseline: 1.7686x; 1.1574x over previous
#include <cuda_runtime.h>
#include <cuda_fp16.h>
#include <math.h>
#include <stdint.h>

// ---------------------------------------------------------------------------
// Scratch (static device arrays; no allocation allowed).
// ---------------------------------------------------------------------------
__device__ __half g_x16[32u * 512u * 512u];    // x  as f16   [B][T][D]
__device__ __half g_h16[32u * 512u * 1024u];   // h  as f16   [B][T][MID]
__device__ __half g_w1h[64u * 512u * 1024u];   // w1 f16      [S][K=D][N=MID]
__device__ __half g_w2h[64u * 1024u * 512u];   // w2 f16      [S][K=MID][N=O]

// ---------------------------------------------------------------------------
// helpers
// ---------------------------------------------------------------------------
__device__ __forceinline__ uint32_t smem_u32(const void* p) {
    uint32_t a;
    asm("{ .reg .u64 t; cvta.to.shared.u64 t, %1; cvt.u32.u64 %0, t; }"
        : "=r"(a) : "l"(p));
    return a;
}

__device__ __forceinline__ void cp_async16(uint32_t saddr, const void* gptr) {
    asm volatile("cp.async.cg.shared.global [%0], [%1], 16;"
                 :: "r"(saddr), "l"(gptr) : "memory");
}
__device__ __forceinline__ void cp_commit() {
    asm volatile("cp.async.commit_group;" ::: "memory");
}
template <int N>
__device__ __forceinline__ void cp_wait() {
    asm volatile("cp.async.wait_group %0;" :: "n"(N) : "memory");
}

__device__ __forceinline__ void ldsm_x4(uint32_t r[4], uint32_t addr) {
    asm volatile("ldmatrix.sync.aligned.m8n8.x4.shared.b16 {%0,%1,%2,%3}, [%4];"
                 : "=r"(r[0]), "=r"(r[1]), "=r"(r[2]), "=r"(r[3])
                 : "r"(addr));
}
__device__ __forceinline__ void ldsm_x4_t(uint32_t r[4], uint32_t addr) {
    asm volatile("ldmatrix.sync.aligned.m8n8.x4.trans.shared.b16 {%0,%1,%2,%3}, [%4];"
                 : "=r"(r[0]), "=r"(r[1]), "=r"(r[2]), "=r"(r[3])
                 : "r"(addr));
}

__device__ __forceinline__ void mma_f16(float c[4], const uint32_t a[4],
                                        uint32_t b0, uint32_t b1) {
    asm volatile(
        "mma.sync.aligned.m16n8k16.row.col.f32.f16.f16.f32 "
        "{%0,%1,%2,%3}, {%4,%5,%6,%7}, {%8,%9}, {%0,%1,%2,%3};"
        : "+f"(c[0]), "+f"(c[1]), "+f"(c[2]), "+f"(c[3])
        : "r"(a[0]), "r"(a[1]), "r"(a[2]), "r"(a[3]), "r"(b0), "r"(b1));
}

// sid dtype sniff (int32 vs int64), proven in rounds 4-14.
__device__ __forceinline__ int load_sid(const int* __restrict__ raw, int b) {
    bool is64 = true;
    #pragma unroll
    for (int i = 0; i < 16; i++)
        if (raw[2 * i + 1] != 0) { is64 = false; break; }
    int s = is64 ? raw[2 * b] : raw[b];
    if (s < 0) s = 0;
    if (s > 63) s = 63;
    return s;
}

__device__ __forceinline__ bool subject_used(const int* __restrict__ raw, int s) {
    bool is64 = true;
    #pragma unroll
    for (int i = 0; i < 16; i++)
        if (raw[2 * i + 1] != 0) { is64 = false; break; }
    #pragma unroll
    for (int b = 0; b < 32; b++) {
        int v = is64 ? raw[2 * b] : raw[b];
        if (v == s) return true;
    }
    return false;
}

// ---------------------------------------------------------------------------
// Conversion kernels (pure streaming)
// ---------------------------------------------------------------------------
__global__ void convert_x_kernel(const float4* __restrict__ in,
                                 uint2* __restrict__ out, int n4) {
    for (int i = blockIdx.x * blockDim.x + threadIdx.x; i < n4;
         i += gridDim.x * blockDim.x) {
        float4 v = in[i];
        __half2 lo = __floats2half2_rn(v.x, v.y);
        __half2 hi = __floats2half2_rn(v.z, v.w);
        uint2 u;
        u.x = *reinterpret_cast<uint32_t*>(&lo);
        u.y = *reinterpret_cast<uint32_t*>(&hi);
        out[i] = u;
    }
}

// w [S][K][N] f32 -> f16 same layout, used subjects only.
__global__ void convert_w_kernel(const float4* __restrict__ in,
                                 uint2* __restrict__ out,
                                 const int* __restrict__ sid_raw,
                                 int elems4_per_subject) {
    const int s = blockIdx.z;
    if (!subject_used(sid_raw, s)) return;
    const float4* ip = in + (size_t)s * elems4_per_subject;
    uint2* op = out + (size_t)s * elems4_per_subject;
    for (int i = blockIdx.x * blockDim.x + threadIdx.x; i < elems4_per_subject;
         i += gridDim.x * blockDim.x) {
        float4 v = ip[i];
        __half2 lo = __floats2half2_rn(v.x, v.y);
        __half2 hi = __floats2half2_rn(v.z, v.w);
        uint2 u;
        u.x = *reinterpret_cast<uint32_t*>(&lo);
        u.y = *reinterpret_cast<uint32_t*>(&hi);
        op[i] = u;
    }
}

// ---------------------------------------------------------------------------
// fp16 mma.sync GEMM, r11 shape (CTA 128x128, 256 thr, 8 warps 4(m)x2(n),
// warp 32x64), NSTAGE=4 with the mainloop unrolled by NSTAGE so every stage
// index / smem slot address is a compile-time constant and producer GMEM
// pointers advance by increments (no per-chunk modulo or k*N multiply).
// Sync order per chunk (r11-proven): cp_wait -> __syncthreads -> issue next
// stage (constant slot) -> LDSM -> MMA.
//   A: [B, M, K] f16 (K contig) -> ldmatrix;  W: [S, K, N] f16 (N contig)
//   -> ldmatrix.trans.
//   A rows: 32B data + 16B pad = 48B stride; B rows: 256B data + 16B pad =
//   272B stride (68 words; 68 mod 32 = 4 -> conflict-free LDSM phases).
//   Requires K % (16*NSTAGE) == 0 (K = 512, 1024 -> NC = 32, 64; both ok).
// ---------------------------------------------------------------------------
#define NSTAGE 4
static constexpr int A_ROW_B = 48;
static constexpr int B_ROW_B = 272;
static constexpr int A_STG = 128 * A_ROW_B;       // 6144 B
static constexpr int B_STG = 16 * B_ROW_B;        // 4352 B
static constexpr int STG_B = A_STG + B_STG;       // 10496 B
static constexpr int SMEM_DYN = NSTAGE * STG_B;   // 41984 B

template <bool DO_GELU, bool DO_BIAS, bool STORE_HALF>
__global__ __launch_bounds__(256, 2)
void subject_hgemm(const __half* __restrict__ A_base,
                   const __half* __restrict__ W_base,
                   const int* __restrict__ sid_raw,
                   const float* __restrict__ bias_base,
                   void* __restrict__ C_base,
                   int M, int N, int K)
{
    const int b = blockIdx.z;
    const int s = load_sid(sid_raw, b);
    const __half* A = A_base + (size_t)b * M * K;
    const __half* W = W_base + (size_t)s * K * N;
    const int m0 = blockIdx.y * 128;
    const int n0 = blockIdx.x * 128;

    extern __shared__ char dsm[];
    const uint32_t smem0 = smem_u32(dsm);

    const int tid = threadIdx.x;
    const int wid = tid >> 5;
    const int lane = tid & 31;
    const int wm = wid >> 1;   // 0..3 -> 32-row slab
    const int wn = wid & 1;    // 0..1 -> 64-col slab
    const int g = lane >> 2;   // 0..7
    const int t4 = lane & 3;   // 0..3

    // cp.async A: thread -> m-row tid>>1, 16B half tid&1.
    const int aR = tid >> 1, aH = tid & 1;
    const uint32_t cpOffA = (uint32_t)(aR * A_ROW_B + aH * 16);
    // cp.async B: thread -> k-row tid>>4, 16B segment tid&15 (coalesced in n).
    const int bR = tid >> 4, bS = tid & 15;
    const uint32_t cpOffB = (uint32_t)(A_STG + bR * B_ROW_B + bS * 16);

    // Producer pointers: advance by 16 (A) / 16*N (B) halves per chunk.
    const __half* AgP = A + (size_t)(m0 + aR) * K + aH * 8;
    const __half* BgP = W + (size_t)bR * N + n0 + bS * 8;
    const ptrdiff_t bStep = (ptrdiff_t)16 * N;

    // ldmatrix lane addresses.
    const uint32_t aAddr0 = smem0
        + (uint32_t)((wm * 32 + (lane & 15)) * A_ROW_B + (lane >> 4) * 16);
    const int bRow = ((lane >> 3) & 1) * 8 + (lane & 7);  // k row within 16
    const int bNh = (lane >> 4) * 8;                       // n sub-offset
    const uint32_t bAddr0 = smem0
        + (uint32_t)(A_STG + bRow * B_ROW_B + (wn * 64 + bNh) * 2);

    const int NC = K / 16;   // 32 or 64; divisible by NSTAGE=4

    float acc[2][8][4];
    #pragma unroll
    for (int i = 0; i < 2; i++)
        #pragma unroll
        for (int j = 0; j < 8; j++)
            #pragma unroll
            for (int q = 0; q < 4; q++)
                acc[i][j][q] = 0.0f;

    // Prologue: issue stages 0..2 into slots 0..2.
    #pragma unroll
    for (int c = 0; c < NSTAGE - 1; c++) {
        cp_async16(smem0 + (uint32_t)(c * STG_B) + cpOffA, AgP);
        cp_async16(smem0 + (uint32_t)(c * STG_B) + cpOffB, BgP);
        cp_commit();
        AgP += 16;
        BgP += bStep;
    }

    #pragma unroll 1
    for (int cc = 0; cc < NC; cc += NSTAGE) {
        #pragma unroll
        for (int ss = 0; ss < NSTAGE; ss++) {
            const int c = cc + ss;

            cp_wait<NSTAGE - 2>();   // stage c complete (own copies)
            __syncthreads();         // publish all threads' copies

            // Issue stage c+3 into slot (ss+3)%4 — compile-time constant.
            if (c + NSTAGE - 1 < NC) {
                constexpr int SLOT_STRIDE = STG_B;
                const uint32_t base =
                    smem0 + (uint32_t)(((ss + NSTAGE - 1) % NSTAGE) * SLOT_STRIDE);
                cp_async16(base + cpOffA, AgP);
                cp_async16(base + cpOffB, BgP);
                AgP += 16;
                BgP += bStep;
            }
            cp_commit();

            const uint32_t soff = (uint32_t)(ss * STG_B);  // constant

            uint32_t af[2][4];
            ldsm_x4(af[0], aAddr0 + soff);
            ldsm_x4(af[1], aAddr0 + soff + 16 * A_ROW_B);

            uint32_t bf[4][4];
            #pragma unroll
            for (int j = 0; j < 4; j++)
                ldsm_x4_t(bf[j], bAddr0 + soff + (uint32_t)(j * 32));

            #pragma unroll
            for (int fm = 0; fm < 2; fm++)
                #pragma unroll
                for (int j = 0; j < 4; j++) {
                    mma_f16(acc[fm][2 * j + 0], af[fm], bf[j][0], bf[j][1]);
                    mma_f16(acc[fm][2 * j + 1], af[fm], bf[j][2], bf[j][3]);
                }
        }
    }

    // ---- epilogue ----
    const float* brow = DO_BIAS ? (bias_base + (size_t)s * N + n0) : nullptr;

    #pragma unroll
    for (int fm = 0; fm < 2; fm++) {
        const int r0 = m0 + wm * 32 + fm * 16 + g;
        #pragma unroll
        for (int fn = 0; fn < 8; fn++) {
            const int col = wn * 64 + fn * 8 + t4 * 2;
            #pragma unroll
            for (int h2 = 0; h2 < 2; h2++) {
                const int row = r0 + 8 * h2;
                float v0 = acc[fm][fn][2 * h2 + 0];
                float v1 = acc[fm][fn][2 * h2 + 1];
                if (DO_BIAS) {
                    v0 += brow[col];
                    v1 += brow[col + 1];
                }
                if (DO_GELU) {
                    v0 = 0.5f * v0 * (1.0f + erff(v0 * 0.70710678118654752f));
                    v1 = 0.5f * v1 * (1.0f + erff(v1 * 0.70710678118654752f));
                }
                if (STORE_HALF) {
                    __half2 hv = __floats2half2_rn(v0, v1);
                    *reinterpret_cast<__half2*>(
                        (__half*)C_base + (size_t)b * M * N +
                        (size_t)row * N + n0 + col) = hv;
                } else {
                    *reinterpret_cast<float2*>(
                        (float*)C_base + (size_t)b * M * N +
                        (size_t)row * N + n0 + col) = make_float2(v0, v1);
                }
            }
        }
    }
}

// ---------------------------------------------------------------------------
extern "C" void kernel_launch(void* const* d_in, const int* in_sizes, int n_in,
                              void* d_out, int out_size) {
    const float* x = (const float*)d_in[0];     // [32, 512, 512]
    const int* sid_raw = (const int*)d_in[1];   // [32] int32 or int64 (sniffed)
    const float* w1 = (const float*)d_in[2];    // [64, 512, 1024]
    const float* w2 = (const float*)d_in[3];    // [64, 1024, 512]
    const float* bias = (const float*)d_in[4];  // [64, 512]
    float* out = (float*)d_out;                 // [32, 512, 512]

    const int B = 32, T = 512, D = 512, MID = 1024, O = 512;
    (void)in_sizes; (void)n_in; (void)out_size;

    __half *x16, *h16, *w1h, *w2h;
    cudaGetSymbolAddress((void**)&x16, g_x16);
    cudaGetSymbolAddress((void**)&h16, g_h16);
    cudaGetSymbolAddress((void**)&w1h, g_w1h);
    cudaGetSymbolAddress((void**)&w2h, g_w2h);

    (void)cudaFuncSetAttribute(
        (const void*)subject_hgemm<true, false, true>,
        cudaFuncAttributeMaxDynamicSharedMemorySize, SMEM_DYN);
    (void)cudaFuncSetAttribute(
        (const void*)subject_hgemm<false, true, false>,
        cudaFuncAttributeMaxDynamicSharedMemorySize, SMEM_DYN);

    // 1) x -> f16
    {
        const int n4 = (B * T * D) / 4;
        convert_x_kernel<<<2048, 256>>>((const float4*)x, (uint2*)x16, n4);
    }
    // 2) w1, w2 -> f16 same layout, used subjects only
    {
        const int e4 = (D * MID) / 4;
        convert_w_kernel<<<dim3(128, 1, 64), 256>>>(
            (const float4*)w1, (uint2*)w1h, sid_raw, e4);
        convert_w_kernel<<<dim3(128, 1, 64), 256>>>(
            (const float4*)w2, (uint2*)w2h, sid_raw, e4);
    }
    // 3) GEMM1 + GELU -> h16:  (M=512, N=1024, K=512)
    {
        dim3 grid(MID / 128, T / 128, B);
        subject_hgemm<true, false, true><<<grid, 256, SMEM_DYN>>>(
            x16, w1h, sid_raw, nullptr, (void*)h16, T, MID, D);
    }
    // 4) GEMM2 + bias -> out f32:  (M=512, N=512, K=1024)
    {
        dim3 grid(O / 128, T / 128, B);
        subject_hgemm<false, true, false><<<grid, 256, SMEM_DYN>>>(
            h16, w2h, sid_raw, bias, (void*)out, T, O, MID);
    }
}